// round 2
// baseline (speedup 1.0000x reference)
#include <cuda_runtime.h>

#define C_M 256
#define C_Z 128
#define NRES 768
#define SDIM 128
#define NBIN 15
#define LN_EPS 1e-5f

static __device__ __forceinline__ float warp_sum(float v) {
#pragma unroll
    for (int o = 16; o; o >>= 1) v += __shfl_xor_sync(0xffffffffu, v, o);
    return v;
}

// ---------------------------------------------------------------------------
// Kernel 1: bulk copy of m rows s=1..S-1 (float4 grid-stride)
// ---------------------------------------------------------------------------
__global__ void k_copy_m(const float4* __restrict__ src, float4* __restrict__ dst,
                         long long n4) {
    long long i = (long long)blockIdx.x * blockDim.x + threadIdx.x;
    long long stride = (long long)gridDim.x * blockDim.x;
    for (; i < n4; i += stride) dst[i] = src[i];
}

// ---------------------------------------------------------------------------
// Kernel 2: m[0,n,:] = m[0,n,:] + LayerNorm(m_prev[0,n,:]) * w + b
// one warp per n-row; 256 channels -> each lane owns 2 float4 (8 floats)
// ---------------------------------------------------------------------------
__global__ void k_m0(const float* __restrict__ m, const float* __restrict__ mp,
                     const float* __restrict__ w, const float* __restrict__ b,
                     float* __restrict__ out) {
    int warp = (blockIdx.x * blockDim.x + threadIdx.x) >> 5;
    int lane = threadIdx.x & 31;
    if (warp >= NRES) return;

    const float4* mp4 = (const float4*)(mp + (size_t)warp * C_M);
    float4 a = mp4[lane];
    float4 c = mp4[lane + 32];

    float s = a.x + a.y + a.z + a.w + c.x + c.y + c.z + c.w;
    s = warp_sum(s);
    float mu = s * (1.0f / C_M);

    float dx0 = a.x - mu, dx1 = a.y - mu, dx2 = a.z - mu, dx3 = a.w - mu;
    float dy0 = c.x - mu, dy1 = c.y - mu, dy2 = c.z - mu, dy3 = c.w - mu;
    float sq = dx0*dx0 + dx1*dx1 + dx2*dx2 + dx3*dx3
             + dy0*dy0 + dy1*dy1 + dy2*dy2 + dy3*dy3;
    sq = warp_sum(sq);
    float rstd = rsqrtf(sq * (1.0f / C_M) + LN_EPS);

    const float4* w4p = (const float4*)w;
    const float4* b4p = (const float4*)b;
    const float4* m4 = (const float4*)(m + (size_t)warp * C_M);
    float4* o4 = (float4*)(out + (size_t)warp * C_M);

    float4 wa = w4p[lane], wb = w4p[lane + 32];
    float4 ba = b4p[lane], bb = b4p[lane + 32];
    float4 ma = m4[lane],  mb = m4[lane + 32];

    float4 r0, r1;
    r0.x = ma.x + dx0 * rstd * wa.x + ba.x;
    r0.y = ma.y + dx1 * rstd * wa.y + ba.y;
    r0.z = ma.z + dx2 * rstd * wa.z + ba.z;
    r0.w = ma.w + dx3 * rstd * wa.w + ba.w;
    r1.x = mb.x + dy0 * rstd * wb.x + bb.x;
    r1.y = mb.y + dy1 * rstd * wb.y + bb.y;
    r1.z = mb.z + dy2 * rstd * wb.z + bb.z;
    r1.w = mb.w + dy3 * rstd * wb.w + bb.w;
    o4[lane] = r0;
    o4[lane + 32] = r1;
}

// ---------------------------------------------------------------------------
// Kernel 3: z[i,j,:] = z + emb(d_ij) + LayerNorm(z_prev[i,j,:]) * w + b
// one warp per (i,j) pair; 128 channels -> one float4 per lane
// ---------------------------------------------------------------------------
__global__ void k_z(const float* __restrict__ z, const float* __restrict__ zp,
                    const float* __restrict__ x,
                    const float* __restrict__ w, const float* __restrict__ b,
                    const float* __restrict__ lw, const float* __restrict__ lb,
                    float* __restrict__ out) {
    long long warp = ((long long)blockIdx.x * blockDim.x + threadIdx.x) >> 5;
    int lane = threadIdx.x & 31;
    if (warp >= (long long)NRES * NRES) return;

    int i = (int)(warp / NRES);
    int j = (int)(warp - (long long)i * NRES);

    // pairwise distance (redundant per lane; x is tiny and L1-resident)
    float dx = x[3 * i + 0] - x[3 * j + 0];
    float dy = x[3 * i + 1] - x[3 * j + 1];
    float dz = x[3 * i + 2] - x[3 * j + 2];
    float d = sqrtf(dx * dx + dy * dy + dz * dz);

    // strict-inequality one-hot binning, exactly like the reference:
    // d must be strictly inside (bl, bu); d outside all bins -> zero one-hot.
    int bin = -1;
#pragma unroll
    for (int k = 0; k < NBIN; k++) {
        float bl = 3.25f + 1.25f * (float)k;
        float bu = (k < NBIN - 1) ? (bl + 1.25f) : 1e8f;
        if (d > bl && d < bu) bin = k;
    }
    // branchless gather: valid ? lw[c*15+bin] : 0
    float sel = (bin >= 0) ? 1.0f : 0.0f;
    int binc = (bin >= 0) ? bin : 0;

    size_t row = (size_t)warp * C_Z;
    float4 z4  = ((const float4*)(z  + row))[lane];
    float4 zp4 = ((const float4*)(zp + row))[lane];

    float s = zp4.x + zp4.y + zp4.z + zp4.w;
    s = warp_sum(s);
    float mu = s * (1.0f / C_Z);

    float d0 = zp4.x - mu, d1 = zp4.y - mu, d2 = zp4.z - mu, d3 = zp4.w - mu;
    float sq = d0*d0 + d1*d1 + d2*d2 + d3*d3;
    sq = warp_sum(sq);
    float rstd = rsqrtf(sq * (1.0f / C_Z) + LN_EPS);

    float4 w4  = ((const float4*)w)[lane];
    float4 b4  = ((const float4*)b)[lane];
    float4 lb4 = ((const float4*)lb)[lane];

    int c0 = lane * 4;
    float e0 = lb4.x + sel * lw[(c0 + 0) * NBIN + binc];
    float e1 = lb4.y + sel * lw[(c0 + 1) * NBIN + binc];
    float e2 = lb4.z + sel * lw[(c0 + 2) * NBIN + binc];
    float e3 = lb4.w + sel * lw[(c0 + 3) * NBIN + binc];

    float4 r;
    r.x = z4.x + e0 + d0 * rstd * w4.x + b4.x;
    r.y = z4.y + e1 + d1 * rstd * w4.y + b4.y;
    r.z = z4.z + e2 + d2 * rstd * w4.z + b4.z;
    r.w = z4.w + e3 + d3 * rstd * w4.w + b4.w;
    ((float4*)(out + row))[lane] = r;
}

extern "C" void kernel_launch(void* const* d_in, const int* in_sizes, int n_in,
                              void* d_out, int out_size) {
    const float* m      = (const float*)d_in[0];   // [S, N, C_M]
    const float* z      = (const float*)d_in[1];   // [N, N, C_Z]
    const float* m_prev = (const float*)d_in[2];   // [S, N, C_M]
    const float* z_prev = (const float*)d_in[3];   // [N, N, C_Z]
    const float* x_prev = (const float*)d_in[4];   // [N, 3]
    const float* ln_m_w = (const float*)d_in[5];
    const float* ln_m_b = (const float*)d_in[6];
    const float* ln_z_w = (const float*)d_in[7];
    const float* ln_z_b = (const float*)d_in[8];
    const float* lin_w  = (const float*)d_in[9];   // [C_Z, 15]
    const float* lin_b  = (const float*)d_in[10];  // [C_Z]

    float* out_m = (float*)d_out;
    float* out_z = out_m + (size_t)SDIM * NRES * C_M;   // m first, z second

    // m rows s = 1..S-1: straight copy (grid-stride float4)
    {
        long long off4 = (long long)NRES * C_M / 4;                 // skip row 0
        long long n4 = (long long)(SDIM - 1) * NRES * C_M / 4;      // 6,242,304
        int threads = 512;
        int blocks = 148 * 16;                                      // ~2.6 f4/thread
        k_copy_m<<<blocks, threads>>>(((const float4*)m) + off4,
                                      ((float4*)out_m) + off4, n4);
    }

    // m row 0 with LayerNorm add: 768 warps
    {
        int threads = 256;
        int blocks = (NRES * 32 + threads - 1) / threads;           // 96
        k_m0<<<blocks, threads>>>(m, m_prev, ln_m_w, ln_m_b, out_m);
    }

    // z: 768*768 warps
    {
        int threads = 256;
        long long warps = (long long)NRES * NRES;
        int blocks = (int)((warps * 32 + threads - 1) / threads);   // 73,728
        k_z<<<blocks, threads>>>(z, z_prev, x_prev, ln_z_w, ln_z_b,
                                 lin_w, lin_b, out_z);
    }
}

// round 3
// speedup vs baseline: 1.0911x; 1.0911x over previous
#include <cuda_runtime.h>

#define C_M 256
#define C_Z 128
#define NRES 768
#define SDIM 128
#define NBIN 15
#define LN_EPS 1e-5f

// block layout of the fused kernel (256 threads = 8 warps everywhere)
#define CB 2368                      // copy blocks (grid-stride float4)
#define MB (NRES / 8)                // 96 m0 blocks, warp per row
#define ZB (NRES * NRES / 8)         // 73728 z blocks, warp per (i,j)

static __device__ __forceinline__ void warp_sum2(float& a, float& b) {
#pragma unroll
    for (int o = 16; o; o >>= 1) {
        a += __shfl_xor_sync(0xffffffffu, a, o);
        b += __shfl_xor_sync(0xffffffffu, b, o);
    }
}

__global__ void __launch_bounds__(256)
fused_kernel(const float* __restrict__ m, const float* __restrict__ z,
             const float* __restrict__ mp, const float* __restrict__ zp,
             const float* __restrict__ x,
             const float* __restrict__ mw, const float* __restrict__ mb,
             const float* __restrict__ zw, const float* __restrict__ zb,
             const float* __restrict__ lw, const float* __restrict__ lb,
             float* __restrict__ out_m, float* __restrict__ out_z) {
    int b = blockIdx.x;
    int wid = threadIdx.x >> 5;
    int lane = threadIdx.x & 31;

    if (b < CB) {
        // ------------------------------------------------------------------
        // Phase A: bulk copy of m rows s=1..S-1 (float4 grid-stride)
        // ------------------------------------------------------------------
        const long long off4 = (long long)NRES * C_M / 4;
        const long long n4 = (long long)(SDIM - 1) * NRES * C_M / 4;
        const float4* src = ((const float4*)m) + off4;
        float4* dst = ((float4*)out_m) + off4;
        long long i = (long long)b * blockDim.x + threadIdx.x;
        long long stride = (long long)CB * blockDim.x;
        for (; i < n4; i += stride) dst[i] = src[i];
        return;
    }

    if (b < CB + MB) {
        // ------------------------------------------------------------------
        // Phase B: m[0,n,:] += LayerNorm(m_prev[0,n,:]) ; warp per row n
        // ------------------------------------------------------------------
        int row = (b - CB) * 8 + wid;

        const float4* mp4 = (const float4*)(mp + (size_t)row * C_M);
        float4 a = mp4[lane];
        float4 c = mp4[lane + 32];

        float s  = a.x + a.y + a.z + a.w + c.x + c.y + c.z + c.w;
        float sq = a.x*a.x + a.y*a.y + a.z*a.z + a.w*a.w
                 + c.x*c.x + c.y*c.y + c.z*c.z + c.w*c.w;
        warp_sum2(s, sq);
        float mu = s * (1.0f / C_M);
        float var = sq * (1.0f / C_M) - mu * mu;
        float rstd = rsqrtf(fmaxf(var, 0.0f) + LN_EPS);

        const float4* w4p = (const float4*)mw;
        const float4* b4p = (const float4*)mb;
        const float4* m4 = (const float4*)(m + (size_t)row * C_M);
        float4* o4 = (float4*)(out_m + (size_t)row * C_M);

        float4 wa = w4p[lane], wb2 = w4p[lane + 32];
        float4 ba = b4p[lane], bb2 = b4p[lane + 32];
        float4 ma = m4[lane],  mb2 = m4[lane + 32];

        float4 r0, r1;
        r0.x = ma.x + (a.x - mu) * rstd * wa.x + ba.x;
        r0.y = ma.y + (a.y - mu) * rstd * wa.y + ba.y;
        r0.z = ma.z + (a.z - mu) * rstd * wa.z + ba.z;
        r0.w = ma.w + (a.w - mu) * rstd * wa.w + ba.w;
        r1.x = mb2.x + (c.x - mu) * rstd * wb2.x + bb2.x;
        r1.y = mb2.y + (c.y - mu) * rstd * wb2.y + bb2.y;
        r1.z = mb2.z + (c.z - mu) * rstd * wb2.z + bb2.z;
        r1.w = mb2.w + (c.w - mu) * rstd * wb2.w + bb2.w;
        o4[lane] = r0;
        o4[lane + 32] = r1;
        return;
    }

    // ----------------------------------------------------------------------
    // Phase C: z[i,j,:] = z + emb(d_ij) + LayerNorm(z_prev[i,j,:])
    // one warp per (i,j) pair; 128 channels -> one float4 per lane
    // ----------------------------------------------------------------------
    long long warp = (long long)(b - CB - MB) * 8 + wid;
    int i = (int)(warp / NRES);
    int j = (int)(warp - (long long)i * NRES);

    size_t row = (size_t)warp * C_Z;
    float4 z4  = ((const float4*)(z  + row))[lane];
    float4 zp4 = ((const float4*)(zp + row))[lane];

    // pairwise distance (redundant per lane; x is tiny and L1-resident)
    float dx = x[3 * i + 0] - x[3 * j + 0];
    float dy = x[3 * i + 1] - x[3 * j + 1];
    float dz = x[3 * i + 2] - x[3 * j + 2];
    float d = sqrtf(dx * dx + dy * dy + dz * dz);

    // strict-inequality one-hot binning, exactly like the reference:
    // d must lie strictly inside (bl, bu); outside all bins -> zero one-hot.
    int bin = -1;
#pragma unroll
    for (int k = 0; k < NBIN; k++) {
        float bl = 3.25f + 1.25f * (float)k;
        float bu = (k < NBIN - 1) ? (bl + 1.25f) : 1e8f;
        if (d > bl && d < bu) bin = k;
    }
    float sel = (bin >= 0) ? 1.0f : 0.0f;
    int binc = (bin >= 0) ? bin : 0;

    float s  = zp4.x + zp4.y + zp4.z + zp4.w;
    float sq = zp4.x*zp4.x + zp4.y*zp4.y + zp4.z*zp4.z + zp4.w*zp4.w;
    warp_sum2(s, sq);
    float mu = s * (1.0f / C_Z);
    float var = sq * (1.0f / C_Z) - mu * mu;
    float rstd = rsqrtf(fmaxf(var, 0.0f) + LN_EPS);

    float4 w4  = ((const float4*)zw)[lane];
    float4 b4  = ((const float4*)zb)[lane];
    float4 lb4 = ((const float4*)lb)[lane];

    int c0 = lane * 4;
    float e0 = lb4.x + sel * lw[(c0 + 0) * NBIN + binc];
    float e1 = lb4.y + sel * lw[(c0 + 1) * NBIN + binc];
    float e2 = lb4.z + sel * lw[(c0 + 2) * NBIN + binc];
    float e3 = lb4.w + sel * lw[(c0 + 3) * NBIN + binc];

    float4 r;
    r.x = z4.x + e0 + (zp4.x - mu) * rstd * w4.x + b4.x;
    r.y = z4.y + e1 + (zp4.y - mu) * rstd * w4.y + b4.y;
    r.z = z4.z + e2 + (zp4.z - mu) * rstd * w4.z + b4.z;
    r.w = z4.w + e3 + (zp4.w - mu) * rstd * w4.w + b4.w;
    ((float4*)(out_z + row))[lane] = r;
}

extern "C" void kernel_launch(void* const* d_in, const int* in_sizes, int n_in,
                              void* d_out, int out_size) {
    const float* m      = (const float*)d_in[0];   // [S, N, C_M]
    const float* z      = (const float*)d_in[1];   // [N, N, C_Z]
    const float* m_prev = (const float*)d_in[2];   // [S, N, C_M]
    const float* z_prev = (const float*)d_in[3];   // [N, N, C_Z]
    const float* x_prev = (const float*)d_in[4];   // [N, 3]
    const float* ln_m_w = (const float*)d_in[5];
    const float* ln_m_b = (const float*)d_in[6];
    const float* ln_z_w = (const float*)d_in[7];
    const float* ln_z_b = (const float*)d_in[8];
    const float* lin_w  = (const float*)d_in[9];   // [C_Z, 15]
    const float* lin_b  = (const float*)d_in[10];  // [C_Z]

    float* out_m = (float*)d_out;
    float* out_z = out_m + (size_t)SDIM * NRES * C_M;   // m first, z second

    int blocks = CB + MB + ZB;   // 2368 + 96 + 73728 = 76192
    fused_kernel<<<blocks, 256>>>(m, z, m_prev, z_prev, x_prev,
                                  ln_m_w, ln_m_b, ln_z_w, ln_z_b,
                                  lin_w, lin_b, out_m, out_z);
}

// round 6
// speedup vs baseline: 1.1563x; 1.0598x over previous
#include <cuda_runtime.h>

#define C_M 256
#define C_Z 128
#define NRES 768
#define SDIM 128
#define NBIN 15
#define LN_EPS 1e-5f

// block layout of the fused kernel (256 threads = 8 warps everywhere)
#define CB 2368                      // copy blocks (grid-stride float4)
#define MB (NRES / 8)                // 96 m0 blocks, warp per row
#define ZB (NRES * NRES / 8)         // 73728 z blocks, warp per (i,j)

// scratch: precomputed per-pair bin and per-bin embedding row
__device__ unsigned char g_bins[NRES * NRES];      // 590 KB
__device__ float g_embT[16 * C_Z];                 // 8 KB: embT[bin][c], bin 15 = invalid

static __device__ __forceinline__ void warp_sum2(float& a, float& b) {
#pragma unroll
    for (int o = 16; o; o >>= 1) {
        a += __shfl_xor_sync(0xffffffffu, a, o);
        b += __shfl_xor_sync(0xffffffffu, b, o);
    }
}

// ---------------------------------------------------------------------------
// Prep kernel: bins[i][j] (strict-inequality binning, exactly like reference)
// and embT[bin][c] = lb[c] + lw[c*15+bin]  (bin 15 -> lb[c] only)
// ---------------------------------------------------------------------------
__global__ void __launch_bounds__(256)
prep_kernel(const float* __restrict__ x,
            const float* __restrict__ lw, const float* __restrict__ lb) {
    int b = blockIdx.x;
    if (b < NRES) {
        int i = b;
        float xi = x[3 * i + 0], yi = x[3 * i + 1], zi = x[3 * i + 2];
#pragma unroll
        for (int t = 0; t < 3; t++) {
            int j = threadIdx.x + t * 256;
            float dx = xi - x[3 * j + 0];
            float dy = yi - x[3 * j + 1];
            float dz = zi - x[3 * j + 2];
            float d = sqrtf(dx * dx + dy * dy + dz * dz);
            int bin = 15;  // 15 = no bin hit -> zero one-hot
#pragma unroll
            for (int k = 0; k < NBIN; k++) {
                float bl = 3.25f + 1.25f * (float)k;
                float bu = (k < NBIN - 1) ? (bl + 1.25f) : 1e8f;
                if (d > bl && d < bu) bin = k;
            }
            g_bins[i * NRES + j] = (unsigned char)bin;
        }
    } else {
        // one extra block builds the 16 x 128 embedding table
        for (int idx = threadIdx.x; idx < 16 * C_Z; idx += 256) {
            int bin = idx >> 7;          // 0..15
            int c = idx & (C_Z - 1);
            float v = lb[c];
            if (bin < NBIN) v += lw[c * NBIN + bin];
            g_embT[bin * C_Z + c] = v;
        }
    }
}

// ---------------------------------------------------------------------------
// Fused main kernel: phase A copy | phase B m0 LN-add | phase C z update
// ---------------------------------------------------------------------------
__global__ void __launch_bounds__(256)
fused_kernel(const float* __restrict__ m, const float* __restrict__ z,
             const float* __restrict__ mp, const float* __restrict__ zp,
             const float* __restrict__ mw, const float* __restrict__ mb,
             const float* __restrict__ zw, const float* __restrict__ zb,
             float* __restrict__ out_m, float* __restrict__ out_z) {
    int b = blockIdx.x;
    int wid = threadIdx.x >> 5;
    int lane = threadIdx.x & 31;

    if (b < CB) {
        // Phase A: bulk copy of m rows s=1..S-1 (float4 grid-stride, streaming)
        const long long off4 = (long long)NRES * C_M / 4;
        const long long n4 = (long long)(SDIM - 1) * NRES * C_M / 4;
        const float4* src = ((const float4*)m) + off4;
        float4* dst = ((float4*)out_m) + off4;
        long long i = (long long)b * blockDim.x + threadIdx.x;
        long long stride = (long long)CB * blockDim.x;
        for (; i < n4; i += stride) __stcs(dst + i, __ldcs(src + i));
        return;
    }

    if (b < CB + MB) {
        // Phase B: m[0,n,:] += LayerNorm(m_prev[0,n,:]) ; warp per row n
        int row = (b - CB) * 8 + wid;

        const float4* mp4 = (const float4*)(mp + (size_t)row * C_M);
        float4 a = mp4[lane];
        float4 c = mp4[lane + 32];

        float s  = a.x + a.y + a.z + a.w + c.x + c.y + c.z + c.w;
        float sq = a.x*a.x + a.y*a.y + a.z*a.z + a.w*a.w
                 + c.x*c.x + c.y*c.y + c.z*c.z + c.w*c.w;
        warp_sum2(s, sq);
        float mu = s * (1.0f / C_M);
        float var = sq * (1.0f / C_M) - mu * mu;
        float rstd = rsqrtf(fmaxf(var, 0.0f) + LN_EPS);

        const float4* w4p = (const float4*)mw;
        const float4* b4p = (const float4*)mb;
        const float4* m4 = (const float4*)(m + (size_t)row * C_M);
        float4* o4 = (float4*)(out_m + (size_t)row * C_M);

        float4 wa = w4p[lane], wb2 = w4p[lane + 32];
        float4 ba = b4p[lane], bb2 = b4p[lane + 32];
        float4 ma = m4[lane],  mb2 = m4[lane + 32];

        float4 r0, r1;
        r0.x = ma.x + (a.x - mu) * rstd * wa.x + ba.x;
        r0.y = ma.y + (a.y - mu) * rstd * wa.y + ba.y;
        r0.z = ma.z + (a.z - mu) * rstd * wa.z + ba.z;
        r0.w = ma.w + (a.w - mu) * rstd * wa.w + ba.w;
        r1.x = mb2.x + (c.x - mu) * rstd * wb2.x + bb2.x;
        r1.y = mb2.y + (c.y - mu) * rstd * wb2.y + bb2.y;
        r1.z = mb2.z + (c.z - mu) * rstd * wb2.z + bb2.z;
        r1.w = mb2.w + (c.w - mu) * rstd * wb2.w + bb2.w;
        o4[lane] = r0;
        o4[lane + 32] = r1;
        return;
    }

    // Phase C: z[i,j,:] = z + embT[bin(i,j)] + LayerNorm(z_prev[i,j,:])
    // one warp per (i,j) pair; 128 channels -> one float4 per lane
    long long warp = (long long)(b - CB - MB) * 8 + wid;

    size_t row = (size_t)warp * C_Z;
    float4 z4  = __ldcs((const float4*)(z  + row) + lane);
    float4 zp4 = __ldcs((const float4*)(zp + row) + lane);

    int bin = __ldg(&g_bins[warp]);                           // broadcast byte
    float4 e4 = ((const float4*)(g_embT + bin * C_Z))[lane];  // coalesced, L1-hot

    float s  = zp4.x + zp4.y + zp4.z + zp4.w;
    float sq = zp4.x*zp4.x + zp4.y*zp4.y + zp4.z*zp4.z + zp4.w*zp4.w;
    warp_sum2(s, sq);
    float mu = s * (1.0f / C_Z);
    float var = sq * (1.0f / C_Z) - mu * mu;
    float rstd = rsqrtf(fmaxf(var, 0.0f) + LN_EPS);

    float4 w4 = ((const float4*)zw)[lane];
    float4 b4 = ((const float4*)zb)[lane];

    float4 r;
    r.x = z4.x + e4.x + (zp4.x - mu) * rstd * w4.x + b4.x;
    r.y = z4.y + e4.y + (zp4.y - mu) * rstd * w4.y + b4.y;
    r.z = z4.z + e4.z + (zp4.z - mu) * rstd * w4.z + b4.z;
    r.w = z4.w + e4.w + (zp4.w - mu) * rstd * w4.w + b4.w;
    __stcs((float4*)(out_z + row) + lane, r);
}

extern "C" void kernel_launch(void* const* d_in, const int* in_sizes, int n_in,
                              void* d_out, int out_size) {
    const float* m      = (const float*)d_in[0];   // [S, N, C_M]
    const float* z      = (const float*)d_in[1];   // [N, N, C_Z]
    const float* m_prev = (const float*)d_in[2];   // [S, N, C_M]
    const float* z_prev = (const float*)d_in[3];   // [N, N, C_Z]
    const float* x_prev = (const float*)d_in[4];   // [N, 3]
    const float* ln_m_w = (const float*)d_in[5];
    const float* ln_m_b = (const float*)d_in[6];
    const float* ln_z_w = (const float*)d_in[7];
    const float* ln_z_b = (const float*)d_in[8];
    const float* lin_w  = (const float*)d_in[9];   // [C_Z, 15]
    const float* lin_b  = (const float*)d_in[10];  // [C_Z]

    float* out_m = (float*)d_out;
    float* out_z = out_m + (size_t)SDIM * NRES * C_M;   // m first, z second

    prep_kernel<<<NRES + 1, 256>>>(x_prev, lin_w, lin_b);

    int blocks = CB + MB + ZB;   // 2368 + 96 + 73728 = 76192
    fused_kernel<<<blocks, 256>>>(m, z, m_prev, z_prev,
                                  ln_m_w, ln_m_b, ln_z_w, ln_z_b,
                                  out_m, out_z);
}

// round 7
// speedup vs baseline: 1.2309x; 1.0645x over previous
#include <cuda_runtime.h>

#define C_M 256
#define C_Z 128
#define NRES 768
#define SDIM 128
#define NBIN 15
#define LN_EPS 1e-5f

// block layout of the fused kernel (256 threads = 8 warps everywhere)
#define CB 2368                      // copy blocks (grid-stride float4)
#define MB (NRES / 8)                // 96 m0 blocks, warp per row
#define ZB2 (NRES * NRES / 16)       // 36864 z blocks, warp per 2 (i,j) pairs

// 8 KB embedding table: embT[bin][c] = lb[c] + lw[c*15+bin]; bin 15 = invalid
__device__ float g_embT[16 * C_Z];

static __device__ __forceinline__ void warp_sum4(float& a, float& b, float& c, float& d) {
#pragma unroll
    for (int o = 16; o; o >>= 1) {
        a += __shfl_xor_sync(0xffffffffu, a, o);
        b += __shfl_xor_sync(0xffffffffu, b, o);
        c += __shfl_xor_sync(0xffffffffu, c, o);
        d += __shfl_xor_sync(0xffffffffu, d, o);
    }
}

static __device__ __forceinline__ void warp_sum2(float& a, float& b) {
#pragma unroll
    for (int o = 16; o; o >>= 1) {
        a += __shfl_xor_sync(0xffffffffu, a, o);
        b += __shfl_xor_sync(0xffffffffu, b, o);
    }
}

// ---------------------------------------------------------------------------
// Prep kernel (1 block): embT[bin][c] = lb[c] + lw[c*15+bin] (bin 15 -> lb)
// ---------------------------------------------------------------------------
__global__ void __launch_bounds__(256)
prep_kernel(const float* __restrict__ lw, const float* __restrict__ lb) {
    for (int idx = threadIdx.x; idx < 16 * C_Z; idx += 256) {
        int bin = idx >> 7;          // 0..15
        int c = idx & (C_Z - 1);
        float v = lb[c];
        if (bin < NBIN) v += lw[c * NBIN + bin];
        g_embT[bin * C_Z + c] = v;
    }
}

// ---------------------------------------------------------------------------
// Fused main kernel: phase A copy | phase B m0 LN-add | phase C z update
// ---------------------------------------------------------------------------
__global__ void __launch_bounds__(256)
fused_kernel(const float* __restrict__ m, const float* __restrict__ z,
             const float* __restrict__ mp, const float* __restrict__ zp,
             const float* __restrict__ x,
             const float* __restrict__ mw, const float* __restrict__ mb,
             const float* __restrict__ zw, const float* __restrict__ zb,
             float* __restrict__ out_m, float* __restrict__ out_z) {
    int b = blockIdx.x;
    int wid = threadIdx.x >> 5;
    int lane = threadIdx.x & 31;

    if (b < CB) {
        // Phase A: bulk copy of m rows s=1..S-1, 4-way unrolled for MLP
        const long long off4 = (long long)NRES * C_M / 4;
        const long long n4 = (long long)(SDIM - 1) * NRES * C_M / 4;
        const float4* src = ((const float4*)m) + off4;
        float4* dst = ((float4*)out_m) + off4;
        long long i = (long long)b * blockDim.x + threadIdx.x;
        const long long stride = (long long)CB * blockDim.x;
        for (; i + 3 * stride < n4; i += 4 * stride) {
            float4 v0 = __ldcs(src + i);
            float4 v1 = __ldcs(src + i + stride);
            float4 v2 = __ldcs(src + i + 2 * stride);
            float4 v3 = __ldcs(src + i + 3 * stride);
            __stcs(dst + i, v0);
            __stcs(dst + i + stride, v1);
            __stcs(dst + i + 2 * stride, v2);
            __stcs(dst + i + 3 * stride, v3);
        }
        for (; i < n4; i += stride) __stcs(dst + i, __ldcs(src + i));
        return;
    }

    if (b < CB + MB) {
        // Phase B: m[0,n,:] += LayerNorm(m_prev[0,n,:]) ; warp per row n
        int row = (b - CB) * 8 + wid;

        const float4* mp4 = (const float4*)(mp + (size_t)row * C_M);
        float4 a = mp4[lane];
        float4 c = mp4[lane + 32];

        float s  = a.x + a.y + a.z + a.w + c.x + c.y + c.z + c.w;
        float sq = a.x*a.x + a.y*a.y + a.z*a.z + a.w*a.w
                 + c.x*c.x + c.y*c.y + c.z*c.z + c.w*c.w;
        warp_sum2(s, sq);
        float mu = s * (1.0f / C_M);
        float var = sq * (1.0f / C_M) - mu * mu;
        float rstd = rsqrtf(fmaxf(var, 0.0f) + LN_EPS);

        const float4* w4p = (const float4*)mw;
        const float4* b4p = (const float4*)mb;
        const float4* m4 = (const float4*)(m + (size_t)row * C_M);
        float4* o4 = (float4*)(out_m + (size_t)row * C_M);

        float4 wa = w4p[lane], wb2 = w4p[lane + 32];
        float4 ba = b4p[lane], bb2 = b4p[lane + 32];
        float4 ma = m4[lane],  mb2 = m4[lane + 32];

        float4 r0, r1;
        r0.x = ma.x + (a.x - mu) * rstd * wa.x + ba.x;
        r0.y = ma.y + (a.y - mu) * rstd * wa.y + ba.y;
        r0.z = ma.z + (a.z - mu) * rstd * wa.z + ba.z;
        r0.w = ma.w + (a.w - mu) * rstd * wa.w + ba.w;
        r1.x = mb2.x + (c.x - mu) * rstd * wb2.x + bb2.x;
        r1.y = mb2.y + (c.y - mu) * rstd * wb2.y + bb2.y;
        r1.z = mb2.z + (c.z - mu) * rstd * wb2.z + bb2.z;
        r1.w = mb2.w + (c.w - mu) * rstd * wb2.w + bb2.w;
        o4[lane] = r0;
        o4[lane + 32] = r1;
        return;
    }

    // ------------------------------------------------------------------
    // Phase C: warp handles 2 consecutive pairs p0, p0+1 (rows contiguous)
    // z[p,:] = z + embT[bin(p)] + LayerNorm(z_prev[p,:])
    // ------------------------------------------------------------------
    long long wp = (long long)(b - CB - MB) * 8 + wid;
    long long p0 = wp * 2;

    size_t row = (size_t)p0 * C_Z;           // 64 float4 spanning both pairs
    const float4* zr  = (const float4*)(z  + row);
    const float4* zpr = (const float4*)(zp + row);
    float4 za  = __ldcs(zr  + lane);          // pair 0
    float4 zc  = __ldcs(zr  + lane + 32);     // pair 1
    float4 pa  = __ldcs(zpr + lane);
    float4 pc  = __ldcs(zpr + lane + 32);

    // bin for pair (p0 + lane&1): even lanes pair0, odd lanes pair1
    int p = (int)p0 + (lane & 1);
    int i = p / NRES;
    int j = p - i * NRES;
    float dx = x[3 * i + 0] - x[3 * j + 0];
    float dy = x[3 * i + 1] - x[3 * j + 1];
    float dz = x[3 * i + 2] - x[3 * j + 2];
    float d = sqrtf(dx * dx + dy * dy + dz * dz);
    int bin = 15;  // 15 = no bin hit -> lb only (zero one-hot)
#pragma unroll
    for (int k = 0; k < NBIN; k++) {
        float bl = 3.25f + 1.25f * (float)k;
        float bu = (k < NBIN - 1) ? (bl + 1.25f) : 1e8f;
        if (d > bl && d < bu) bin = k;   // strict inequality, like reference
    }
    int bin0 = __shfl_sync(0xffffffffu, bin, 0);
    int bin1 = __shfl_sync(0xffffffffu, bin, 1);

    float4 e0 = ((const float4*)(g_embT + bin0 * C_Z))[lane];
    float4 e1 = ((const float4*)(g_embT + bin1 * C_Z))[lane];

    float s0 = pa.x + pa.y + pa.z + pa.w;
    float q0 = pa.x*pa.x + pa.y*pa.y + pa.z*pa.z + pa.w*pa.w;
    float s1 = pc.x + pc.y + pc.z + pc.w;
    float q1 = pc.x*pc.x + pc.y*pc.y + pc.z*pc.z + pc.w*pc.w;
    warp_sum4(s0, q0, s1, q1);
    float mu0 = s0 * (1.0f / C_Z);
    float mu1 = s1 * (1.0f / C_Z);
    float r0std = rsqrtf(fmaxf(q0 * (1.0f / C_Z) - mu0 * mu0, 0.0f) + LN_EPS);
    float r1std = rsqrtf(fmaxf(q1 * (1.0f / C_Z) - mu1 * mu1, 0.0f) + LN_EPS);

    float4 w4 = ((const float4*)zw)[lane];
    float4 b4 = ((const float4*)zb)[lane];

    float4 r;
    r.x = za.x + e0.x + (pa.x - mu0) * r0std * w4.x + b4.x;
    r.y = za.y + e0.y + (pa.y - mu0) * r0std * w4.y + b4.y;
    r.z = za.z + e0.z + (pa.z - mu0) * r0std * w4.z + b4.z;
    r.w = za.w + e0.w + (pa.w - mu0) * r0std * w4.w + b4.w;
    __stcs((float4*)(out_z + row) + lane, r);

    float4 r2;
    r2.x = zc.x + e1.x + (pc.x - mu1) * r1std * w4.x + b4.x;
    r2.y = zc.y + e1.y + (pc.y - mu1) * r1std * w4.y + b4.y;
    r2.z = zc.z + e1.z + (pc.z - mu1) * r1std * w4.z + b4.z;
    r2.w = zc.w + e1.w + (pc.w - mu1) * r1std * w4.w + b4.w;
    __stcs((float4*)(out_z + row) + lane + 32, r2);
}

extern "C" void kernel_launch(void* const* d_in, const int* in_sizes, int n_in,
                              void* d_out, int out_size) {
    const float* m      = (const float*)d_in[0];   // [S, N, C_M]
    const float* z      = (const float*)d_in[1];   // [N, N, C_Z]
    const float* m_prev = (const float*)d_in[2];   // [S, N, C_M]
    const float* z_prev = (const float*)d_in[3];   // [N, N, C_Z]
    const float* x_prev = (const float*)d_in[4];   // [N, 3]
    const float* ln_m_w = (const float*)d_in[5];
    const float* ln_m_b = (const float*)d_in[6];
    const float* ln_z_w = (const float*)d_in[7];
    const float* ln_z_b = (const float*)d_in[8];
    const float* lin_w  = (const float*)d_in[9];   // [C_Z, 15]
    const float* lin_b  = (const float*)d_in[10];  // [C_Z]

    float* out_m = (float*)d_out;
    float* out_z = out_m + (size_t)SDIM * NRES * C_M;   // m first, z second

    prep_kernel<<<1, 256>>>(lin_w, lin_b);

    int blocks = CB + MB + ZB2;   // 2368 + 96 + 36864 = 39328
    fused_kernel<<<blocks, 256>>>(m, z, m_prev, z_prev, x_prev,
                                  ln_m_w, ln_m_b, ln_z_w, ln_z_b,
                                  out_m, out_z);
}